// round 2
// baseline (speedup 1.0000x reference)
#include <cuda_runtime.h>
#include <cstddef>

// Problem constants (fixed by the reference: N=1024, D=16, E=16384)
#define D_DIM 16
#define NM    16384   // N * D = 1024 * 16

// Runtime-detected edge_index element width: stride in int32 words (1 = int32, 2 = int64 LE)
__device__ int g_idx_stride;

// Robust dtype detection. The first 65536 int32 words are valid under both
// dtypes (int32: whole (2, 32768) array; int64: all of edge_index[0]).
//   int64 LE: every odd word in [0, 65536) is a high word of a value < 1024 -> 0.
//   int32:    odd words include edge_index[0][16384..] = col values, all >= 1
//             (pairs satisfy row < col), so at least one odd word is nonzero.
__global__ void detect_idx_kernel(const int* __restrict__ eidx32) {
    __shared__ int any_nonzero;
    if (threadIdx.x == 0) any_nonzero = 0;
    __syncthreads();
    int local = 0;
    for (int w = 1 + 2 * threadIdx.x; w < 65536; w += 2 * blockDim.x)
        local |= eidx32[w];
    if (local) atomicOr(&any_nonzero, 1);
    __syncthreads();
    if (threadIdx.x == 0) g_idx_stride = any_nonzero ? 1 : 2;
}

// One CTA (256 threads) per undirected edge e in [0, E).
//   A = maps[e]     (16x16), B = maps[e + E]  (16x16)
//   T  = A^T B   -> -dinv[r]*dinv[c]*T   at block (r,c); -T^T at (c,r)
//   G1 = A^T A   -> dinv[r]^2 * G1 atomically into diag block (r,r)
//   G2 = B^T B   -> dinv[c]^2 * G2 atomically into diag block (c,c)
// Output layout: out[(bi*16 + a) * NM + bj*16 + b] = L[bi, bj, a, b]
__global__ void laplacian_edge_kernel(const float* __restrict__ degrees,
                                      const float* __restrict__ maps,
                                      const int*   __restrict__ eidx32,
                                      float*       __restrict__ out,
                                      int E) {
    __shared__ float Asm[256];
    __shared__ float Bsm[256];
    __shared__ float Tsm[16][17];   // padded to kill bank conflicts on transpose read

    const int e   = blockIdx.x;
    const int tid = threadIdx.x;
    const int j   = tid >> 4;   // output row within block
    const int k   = tid & 15;   // output col within block

    const int stride = g_idx_stride;
    // edge_index shape (2, 2E) row-major: row = [0, e], col = [1, e] -> flat (2E + e)
    const int r = eidx32[(size_t)e * stride];
    const int c = eidx32[(size_t)(2 * E + e) * stride];

    // Stage both 16x16 maps into shared memory (coalesced 1KB loads each)
    Asm[tid] = maps[(size_t)e * 256 + tid];
    Bsm[tid] = maps[((size_t)e + E) * 256 + tid];
    __syncthreads();

    float t = 0.f, g1 = 0.f, g2 = 0.f;
    #pragma unroll
    for (int i = 0; i < 16; ++i) {
        const float aj = Asm[i * 16 + j];   // broadcast within half-warp
        const float ak = Asm[i * 16 + k];   // conflict-free (16 banks, broadcast)
        const float bj = Bsm[i * 16 + j];
        const float bk = Bsm[i * 16 + k];
        t  += aj * bk;   // (A^T B)[j,k]
        g1 += aj * ak;   // (A^T A)[j,k]
        g2 += bj * bk;   // (B^T B)[j,k]
    }

    const float dr = rsqrtf(degrees[r] * (float)D_DIM + 1.0f);
    const float dc = rsqrtf(degrees[c] * (float)D_DIM + 1.0f);
    const float s  = dr * dc;

    // Upper-triangular block (r, c): coalesced row writes
    out[(size_t)(r * 16 + j) * NM + c * 16 + k] = -s * t;

    // Transpose through shared memory so the (c, r) write stays coalesced
    Tsm[j][k] = t;
    __syncthreads();
    out[(size_t)(c * 16 + j) * NM + r * 16 + k] = -s * Tsm[k][j];

    // Diagonal Gram contributions (multiple edges hit the same node: atomic)
    atomicAdd(&out[(size_t)(r * 16 + j) * NM + r * 16 + k], (dr * dr) * g1);
    atomicAdd(&out[(size_t)(c * 16 + j) * NM + c * 16 + k], (dc * dc) * g2);
}

extern "C" void kernel_launch(void* const* d_in, const int* in_sizes, int n_in,
                              void* d_out, int out_size) {
    // Inputs (metadata order): adj_mat [N*N f32], degrees [N f32],
    // maps [2E*16*16 f32], edge_index [2*2E int]
    const float* degrees = (const float*)d_in[1];
    const float* maps    = (const float*)d_in[2];
    const int*   eidx32  = (const int*)d_in[3];
    float*       out     = (float*)d_out;

    const int E = in_sizes[2] / (2 * 256);   // maps has 2E blocks of 256 floats

    // 1) Zero the 1 GiB output (dominant HBM cost; memset is bandwidth-optimal)
    cudaMemsetAsync(d_out, 0, (size_t)out_size * sizeof(float), 0);

    // 2) Detect edge_index storage width (int32 vs int64)
    detect_idx_kernel<<<1, 256>>>(eidx32);

    // 3) Edge-parallel scatter of all nonzero Laplacian blocks
    laplacian_edge_kernel<<<E, 256>>>(degrees, maps, eidx32, out, E);
}